// round 1
// baseline (speedup 1.0000x reference)
#include <cuda_runtime.h>
#include <cuda_bf16.h>
#include <cstdint>
#include <math.h>

// ---------------------------------------------------------------------------
// Binarized CNN (XNOR-net) forward pass.
//
// Pipeline:
//   conv1 (float 3x3, 3->128) + b1 + relu + bn1 -> binarize -> bits1 [128,32,32,4w]
//   bconv2 (128->128) + relu + pool + bn2 -> binarize -> bits2 [128,16,16,4w]
//   bconv3 (128->256) + relu + bn3        -> binarize -> bits3 [128,16,16,8w]
//   bconv4 (256->256) + relu + pool + bn4 -> binarize -> bits4 [128,8,8,8w]
//   bconv5 (256->512) + relu + bn5        -> binarize -> bits5 [128,8,8,16w]
//   bconv6 (512->512) + relu + pool + bn6 -> float h6 [128,4,4,512]
//   dense (512->10) + softmax -> out [128,4,4,10]
//
// Binary conv: activations/weights are sign(x) in {-1,+1}; SAME zero padding
// contributes 0, handled by counting valid taps:
//   dot = valid_taps*Cin - 2 * sum_taps popc(abits ^ wbits)
// ---------------------------------------------------------------------------

#define NB 128

// Scratch (device globals; no allocation allowed)
__device__ uint32_t g_bits1[NB * 32 * 32 * 4];
__device__ uint32_t g_bits2[NB * 16 * 16 * 4];
__device__ uint32_t g_bits3[NB * 16 * 16 * 8];
__device__ uint32_t g_bits4[NB * 8 * 8 * 8];
__device__ uint32_t g_bits5[NB * 8 * 8 * 16];
__device__ float    g_h6[NB * 4 * 4 * 512];
__device__ uint32_t g_wb2[9 * 4 * 128];
__device__ uint32_t g_wb3[9 * 4 * 256];
__device__ uint32_t g_wb4[9 * 8 * 256];
__device__ uint32_t g_wb5[9 * 8 * 512];
__device__ uint32_t g_wb6[9 * 16 * 512];

// ---------------------------------------------------------------------------
// Pack weight signs into bits: layout [tap(9)][cin_word][cout], bit j = cin%32
// w is HWIO: w[((tap)*CIN + ci)*COUT + co]
// ---------------------------------------------------------------------------
__global__ void pack_w_kernel(const float* __restrict__ w, uint32_t* __restrict__ wb,
                              int CIN, int COUT) {
    int idx = blockIdx.x * blockDim.x + threadIdx.x;
    int cw = CIN >> 5;
    int total = 9 * cw * COUT;
    if (idx >= total) return;
    int cout = idx % COUT;
    int tw = idx / COUT;            // tap*cw + wword
    int wword = tw % cw;
    int tap = tw / cw;
    uint32_t m = 0;
#pragma unroll 8
    for (int j = 0; j < 32; j++) {
        float f = w[(tap * CIN + wword * 32 + j) * COUT + cout];
        m |= (f > 0.0f ? 1u : 0u) << j;
    }
    wb[idx] = m;
}

// ---------------------------------------------------------------------------
// conv1: float 3x3 SAME conv (3->128) + bias + relu + bn + binarize + pack
// One block = one pixel, 128 threads = 128 output channels.
// ---------------------------------------------------------------------------
__global__ void conv1_kernel(const float* __restrict__ x, const float* __restrict__ w1,
                             const float* __restrict__ b1, const float* __restrict__ s1,
                             const float* __restrict__ bb1, uint32_t* __restrict__ obits) {
    int p = blockIdx.x;                  // 0 .. 128*32*32-1
    int co = threadIdx.x;                // 0..127
    int xx = p & 31;
    int y = (p >> 5) & 31;
    int n = p >> 10;
    float acc = 0.0f;
#pragma unroll
    for (int ky = 0; ky < 3; ky++) {
        int iy = y + ky - 1;
        if ((unsigned)iy >= 32u) continue;
#pragma unroll
        for (int kx = 0; kx < 3; kx++) {
            int ix = xx + kx - 1;
            if ((unsigned)ix >= 32u) continue;
            const float* xp = x + ((n * 32 + iy) * 32 + ix) * 3;
            const float* wp = w1 + ((ky * 3 + kx) * 3) * 128 + co;
            acc = fmaf(xp[0], wp[0], acc);
            acc = fmaf(xp[1], wp[128], acc);
            acc = fmaf(xp[2], wp[256], acc);
        }
    }
    float v = fmaxf(acc + b1[co], 0.0f);
    v = fmaf(v, s1[co], bb1[co]);
    unsigned mask = __ballot_sync(0xffffffffu, v > 0.0f);
    if ((co & 31) == 0) obits[p * 4 + (co >> 5)] = mask;
}

// ---------------------------------------------------------------------------
// Generic binary conv layer.
// WW = Cin/32 words. Grid: x = npix_out/(8 warps * 4 ppw), y = COUT/32 groups.
// Each warp: 4 output pixels; each lane: one output channel of its group.
// Weights for this group staged in SMEM, layout [tap*WW+w][lane] (stride-1).
// ---------------------------------------------------------------------------
template <int WW, bool POOL, bool FINAL>
__global__ void bconv_kernel(const uint32_t* __restrict__ abits,
                             const uint32_t* __restrict__ wbits,
                             const float* __restrict__ scale,
                             const float* __restrict__ bias,
                             uint32_t* __restrict__ obits,
                             float* __restrict__ ofloat,
                             int N, int H, int Wd, int COUT) {
    constexpr int PPW = 4;
    __shared__ uint32_t sw[9 * WW * 32];
    const int g = blockIdx.y;

    for (int idx = threadIdx.x; idx < 9 * WW * 32; idx += blockDim.x) {
        int tw = idx >> 5, j = idx & 31;
        sw[idx] = wbits[tw * COUT + g * 32 + j];
    }
    __syncthreads();

    const int lane = threadIdx.x & 31;
    const int warp = threadIdx.x >> 5;
    const int Ho = POOL ? (H >> 1) : H;
    const int Wo = POOL ? (Wd >> 1) : Wd;
    const int npix = N * Ho * Wo;
    const int c = g * 32 + lane;
    const float sc = scale[c];
    const float bi = bias[c];

    auto dot = [&](int n, int y, int x) -> int {
        int s = 0, valid = 0;
#pragma unroll
        for (int ky = 0; ky < 3; ky++) {
            int iy = y + ky - 1;
            if ((unsigned)iy >= (unsigned)H) continue;
#pragma unroll
            for (int kx = 0; kx < 3; kx++) {
                int ix = x + kx - 1;
                if ((unsigned)ix >= (unsigned)Wd) continue;
                valid++;
                const uint32_t* ap = abits + ((size_t)(n * H + iy) * Wd + ix) * WW;
                const uint32_t* wp = &sw[(ky * 3 + kx) * WW * 32 + lane];
#pragma unroll
                for (int w = 0; w < WW; w++)
                    s += __popc(__ldg(ap + w) ^ wp[w * 32]);
            }
        }
        return valid * WW * 32 - 2 * s;
    };

    int p0 = (blockIdx.x * 8 + warp) * PPW;
    for (int pp = 0; pp < PPW; pp++) {
        int p = p0 + pp;
        if (p >= npix) break;   // warp-uniform
        int xo = p % Wo;
        int t = p / Wo;
        int yo = t % Ho;
        int n = t / Ho;

        int m;
        if (POOL) {
            m = 0;  // relu(max) == max(relu, 0), accumulator is integer
            m = max(m, dot(n, 2 * yo + 0, 2 * xo + 0));
            m = max(m, dot(n, 2 * yo + 0, 2 * xo + 1));
            m = max(m, dot(n, 2 * yo + 1, 2 * xo + 0));
            m = max(m, dot(n, 2 * yo + 1, 2 * xo + 1));
        } else {
            m = max(dot(n, yo, xo), 0);
        }
        float val = fmaf((float)m, sc, bi);
        if (FINAL) {
            ofloat[(size_t)p * COUT + c] = val;
        } else {
            unsigned mask = __ballot_sync(0xffffffffu, val > 0.0f);
            if (lane == 0) obits[p * (COUT >> 5) + g] = mask;
        }
    }
}

// ---------------------------------------------------------------------------
// Dense (512->10) + softmax, one warp per output pixel.
// ---------------------------------------------------------------------------
__global__ void dense_softmax_kernel(const float* __restrict__ h, const float* __restrict__ dw,
                                     const float* __restrict__ db, float* __restrict__ out) {
    int warp = (blockIdx.x * blockDim.x + threadIdx.x) >> 5;
    int lane = threadIdx.x & 31;
    if (warp >= NB * 4 * 4) return;
    float acc[10];
#pragma unroll
    for (int j = 0; j < 10; j++) acc[j] = 0.0f;
    const float* hp = h + (size_t)warp * 512;
#pragma unroll
    for (int k = 0; k < 16; k++) {
        int cc = k * 32 + lane;
        float hv = hp[cc];
        const float* wp = dw + cc * 10;
#pragma unroll
        for (int j = 0; j < 10; j++) acc[j] = fmaf(hv, __ldg(wp + j), acc[j]);
    }
#pragma unroll
    for (int s = 16; s > 0; s >>= 1) {
#pragma unroll
        for (int j = 0; j < 10; j++) acc[j] += __shfl_xor_sync(0xffffffffu, acc[j], s);
    }
    if (lane == 0) {
        float l[10], m = -1e30f;
#pragma unroll
        for (int j = 0; j < 10; j++) { l[j] = acc[j] + db[j]; m = fmaxf(m, l[j]); }
        float sum = 0.0f;
#pragma unroll
        for (int j = 0; j < 10; j++) { l[j] = expf(l[j] - m); sum += l[j]; }
        float inv = 1.0f / sum;
#pragma unroll
        for (int j = 0; j < 10; j++) out[warp * 10 + j] = l[j] * inv;
    }
}

// ---------------------------------------------------------------------------
// Launch
// Input order (setup_inputs dict order):
//  0:x 1:w1 2:b1 3:w2 4:w3 5:w4 6:w5 7:w6
//  8:bn1_s 9:bn1_b 10:bn2_s 11:bn2_b 12:bn3_s 13:bn3_b
//  14:bn4_s 15:bn4_b 16:bn5_s 17:bn5_b 18:bn6_s 19:bn6_b
//  20:dense_w 21:dense_b
// ---------------------------------------------------------------------------
extern "C" void kernel_launch(void* const* d_in, const int* in_sizes, int n_in,
                              void* d_out, int out_size) {
    const float* x   = (const float*)d_in[0];
    const float* w1  = (const float*)d_in[1];
    const float* b1  = (const float*)d_in[2];
    const float* w2  = (const float*)d_in[3];
    const float* w3  = (const float*)d_in[4];
    const float* w4  = (const float*)d_in[5];
    const float* w5  = (const float*)d_in[6];
    const float* w6  = (const float*)d_in[7];
    const float* bn1s = (const float*)d_in[8];
    const float* bn1b = (const float*)d_in[9];
    const float* bn2s = (const float*)d_in[10];
    const float* bn2b = (const float*)d_in[11];
    const float* bn3s = (const float*)d_in[12];
    const float* bn3b = (const float*)d_in[13];
    const float* bn4s = (const float*)d_in[14];
    const float* bn4b = (const float*)d_in[15];
    const float* bn5s = (const float*)d_in[16];
    const float* bn5b = (const float*)d_in[17];
    const float* bn6s = (const float*)d_in[18];
    const float* bn6b = (const float*)d_in[19];
    const float* dw   = (const float*)d_in[20];
    const float* db   = (const float*)d_in[21];
    float* out = (float*)d_out;

    uint32_t *bits1, *bits2, *bits3, *bits4, *bits5;
    uint32_t *wb2, *wb3, *wb4, *wb5, *wb6;
    float* h6;
    cudaGetSymbolAddress((void**)&bits1, g_bits1);
    cudaGetSymbolAddress((void**)&bits2, g_bits2);
    cudaGetSymbolAddress((void**)&bits3, g_bits3);
    cudaGetSymbolAddress((void**)&bits4, g_bits4);
    cudaGetSymbolAddress((void**)&bits5, g_bits5);
    cudaGetSymbolAddress((void**)&wb2, g_wb2);
    cudaGetSymbolAddress((void**)&wb3, g_wb3);
    cudaGetSymbolAddress((void**)&wb4, g_wb4);
    cudaGetSymbolAddress((void**)&wb5, g_wb5);
    cudaGetSymbolAddress((void**)&wb6, g_wb6);
    cudaGetSymbolAddress((void**)&h6, g_h6);

    // Pack weight sign bits (cheap, deterministic, per-launch)
    pack_w_kernel<<<(9 * 4 * 128 + 255) / 256, 256>>>(w2, wb2, 128, 128);
    pack_w_kernel<<<(9 * 4 * 256 + 255) / 256, 256>>>(w3, wb3, 128, 256);
    pack_w_kernel<<<(9 * 8 * 256 + 255) / 256, 256>>>(w4, wb4, 256, 256);
    pack_w_kernel<<<(9 * 8 * 512 + 255) / 256, 256>>>(w5, wb5, 256, 512);
    pack_w_kernel<<<(9 * 16 * 512 + 255) / 256, 256>>>(w6, wb6, 512, 512);

    // conv1 + relu + bn1 + binarize
    conv1_kernel<<<NB * 32 * 32, 128>>>(x, w1, b1, bn1s, bn1b, bits1);

    // bconv2 (128->128) + pool + bn2
    bconv_kernel<4, true, false><<<dim3(NB * 16 * 16 / 32, 4), 256>>>(
        bits1, wb2, bn2s, bn2b, bits2, nullptr, NB, 32, 32, 128);
    // bconv3 (128->256) + bn3
    bconv_kernel<4, false, false><<<dim3(NB * 16 * 16 / 32, 8), 256>>>(
        bits2, wb3, bn3s, bn3b, bits3, nullptr, NB, 16, 16, 256);
    // bconv4 (256->256) + pool + bn4
    bconv_kernel<8, true, false><<<dim3(NB * 8 * 8 / 32, 8), 256>>>(
        bits3, wb4, bn4s, bn4b, bits4, nullptr, NB, 16, 16, 256);
    // bconv5 (256->512) + bn5
    bconv_kernel<8, false, false><<<dim3(NB * 8 * 8 / 32, 16), 256>>>(
        bits4, wb5, bn5s, bn5b, bits5, nullptr, NB, 8, 8, 512);
    // bconv6 (512->512) + pool + bn6 -> float
    bconv_kernel<16, true, true><<<dim3(NB * 4 * 4 / 32, 16), 256>>>(
        bits5, wb6, bn6s, bn6b, nullptr, h6, NB, 8, 8, 512);

    // dense + softmax
    dense_softmax_kernel<<<NB * 4 * 4 * 32 / 256, 256>>>(h6, dw, db, out);
}

// round 2
// speedup vs baseline: 1.1571x; 1.1571x over previous
#include <cuda_runtime.h>
#include <cuda_bf16.h>
#include <cstdint>
#include <math.h>

// ---------------------------------------------------------------------------
// Binarized CNN (XNOR-net) forward pass. Bit-packed XNOR-popcount convs.
//   dot = valid_taps*Cin - 2 * sum_taps popc(abits ^ wbits)
// R2: vectorized LDG.128 activation loads + LDS.128 weight loads
//     (SMEM layout [tap][w4][lane][4w]), fused weight-pack kernel.
// ---------------------------------------------------------------------------

#define NB 128

// Scratch (device globals; no allocation allowed)
__device__ uint32_t g_bits1[NB * 32 * 32 * 4];
__device__ uint32_t g_bits2[NB * 16 * 16 * 4];
__device__ uint32_t g_bits3[NB * 16 * 16 * 8];
__device__ uint32_t g_bits4[NB * 8 * 8 * 8];
__device__ uint32_t g_bits5[NB * 8 * 8 * 16];
__device__ float    g_h6[NB * 4 * 4 * 512];
__device__ uint32_t g_wb2[9 * 4 * 128];
__device__ uint32_t g_wb3[9 * 4 * 256];
__device__ uint32_t g_wb4[9 * 8 * 256];
__device__ uint32_t g_wb5[9 * 8 * 512];
__device__ uint32_t g_wb6[9 * 16 * 512];

// ---------------------------------------------------------------------------
// Fused weight-sign packing for all 5 binary layers.
// Output layout per layer: [tap(9)][cin_word][cout], bit j = cin%32.
// ---------------------------------------------------------------------------
__device__ __forceinline__ void pack_one(const float* __restrict__ w,
                                         uint32_t* __restrict__ wb,
                                         int idx, int CIN, int COUT) {
    int cout = idx % COUT;
    int tw = idx / COUT;            // tap*cw + wword
    int cw = CIN >> 5;
    int wword = tw % cw;
    int tap = tw / cw;
    uint32_t m = 0;
#pragma unroll 8
    for (int j = 0; j < 32; j++) {
        float f = w[(tap * CIN + wword * 32 + j) * COUT + cout];
        m |= (f > 0.0f ? 1u : 0u) << j;
    }
    wb[idx] = m;
}

__global__ void pack_all_kernel(const float* __restrict__ w2, const float* __restrict__ w3,
                                const float* __restrict__ w4, const float* __restrict__ w5,
                                const float* __restrict__ w6,
                                uint32_t* __restrict__ wb2, uint32_t* __restrict__ wb3,
                                uint32_t* __restrict__ wb4, uint32_t* __restrict__ wb5,
                                uint32_t* __restrict__ wb6) {
    int idx = blockIdx.x * blockDim.x + threadIdx.x;
    const int n2 = 9 * 4 * 128, n3 = 9 * 4 * 256, n4 = 9 * 8 * 256,
              n5 = 9 * 8 * 512, n6 = 9 * 16 * 512;
    if (idx < n2) { pack_one(w2, wb2, idx, 128, 128); return; }
    idx -= n2;
    if (idx < n3) { pack_one(w3, wb3, idx, 128, 256); return; }
    idx -= n3;
    if (idx < n4) { pack_one(w4, wb4, idx, 256, 256); return; }
    idx -= n4;
    if (idx < n5) { pack_one(w5, wb5, idx, 256, 512); return; }
    idx -= n5;
    if (idx < n6) { pack_one(w6, wb6, idx, 512, 512); return; }
}

// ---------------------------------------------------------------------------
// conv1: float 3x3 SAME conv (3->128) + bias + relu + bn + binarize + pack
// ---------------------------------------------------------------------------
__global__ void conv1_kernel(const float* __restrict__ x, const float* __restrict__ w1,
                             const float* __restrict__ b1, const float* __restrict__ s1,
                             const float* __restrict__ bb1, uint32_t* __restrict__ obits) {
    int p = blockIdx.x;                  // 0 .. 128*32*32-1
    int co = threadIdx.x;                // 0..127
    int xx = p & 31;
    int y = (p >> 5) & 31;
    int n = p >> 10;
    float acc = 0.0f;
#pragma unroll
    for (int ky = 0; ky < 3; ky++) {
        int iy = y + ky - 1;
        if ((unsigned)iy >= 32u) continue;
#pragma unroll
        for (int kx = 0; kx < 3; kx++) {
            int ix = xx + kx - 1;
            if ((unsigned)ix >= 32u) continue;
            const float* xp = x + ((n * 32 + iy) * 32 + ix) * 3;
            const float* wp = w1 + ((ky * 3 + kx) * 3) * 128 + co;
            acc = fmaf(xp[0], wp[0], acc);
            acc = fmaf(xp[1], wp[128], acc);
            acc = fmaf(xp[2], wp[256], acc);
        }
    }
    float v = fmaxf(acc + b1[co], 0.0f);
    v = fmaf(v, s1[co], bb1[co]);
    unsigned mask = __ballot_sync(0xffffffffu, v > 0.0f);
    if ((co & 31) == 0) obits[p * 4 + (co >> 5)] = mask;
}

// ---------------------------------------------------------------------------
// Generic binary conv layer, vectorized.
// WW = Cin/32 words, WG = WW/4 uint4 groups.
// Grid: x = npix_out/(8 warps * 4 ppw), y = COUT/32 groups.
// Weight SMEM layout: sw[(tap*WG + g4)*32 + lane] = uint4 of lane's 4 words.
//   -> each lane LDS.128 at 16B stride: conflict-free per 8-lane phase.
// Activations: uint4 LDG.128 broadcast (all lanes same address).
// ---------------------------------------------------------------------------
template <int WW, bool POOL, bool FINAL>
__global__ void bconv_kernel(const uint32_t* __restrict__ abits,
                             const uint32_t* __restrict__ wbits,
                             const float* __restrict__ scale,
                             const float* __restrict__ bias,
                             uint32_t* __restrict__ obits,
                             float* __restrict__ ofloat,
                             int N, int H, int Wd, int COUT) {
    constexpr int PPW = 4;
    constexpr int WG = WW / 4;
    __shared__ uint4 sw[9 * WG * 32];
    const int g = blockIdx.y;

    // Fill SMEM: flat word f -> (j = f&3, lane = (f>>2)&31, tg = f>>7)
    // tg = tap*WG + g4 ; global word w = g4*4 + j
    {
        uint32_t* sws = (uint32_t*)sw;
        for (int f = threadIdx.x; f < 9 * WW * 32; f += blockDim.x) {
            int j = f & 3;
            int lane = (f >> 2) & 31;
            int tg = f >> 7;
            int tap = tg / WG;
            int g4 = tg - tap * WG;
            int w = g4 * 4 + j;
            sws[f] = wbits[(tap * WW + w) * COUT + g * 32 + lane];
        }
    }
    __syncthreads();

    const int lane = threadIdx.x & 31;
    const int warp = threadIdx.x >> 5;
    const int Ho = POOL ? (H >> 1) : H;
    const int Wo = POOL ? (Wd >> 1) : Wd;
    const int npix = N * Ho * Wo;
    const int c = g * 32 + lane;
    const float sc = scale[c];
    const float bi = bias[c];

    auto dot = [&](int n, int y, int x) -> int {
        int s = 0, valid = 0;
#pragma unroll
        for (int ky = 0; ky < 3; ky++) {
            int iy = y + ky - 1;
            if ((unsigned)iy >= (unsigned)H) continue;
#pragma unroll
            for (int kx = 0; kx < 3; kx++) {
                int ix = x + kx - 1;
                if ((unsigned)ix >= (unsigned)Wd) continue;
                valid++;
                int tap = ky * 3 + kx;
                const uint4* ap =
                    (const uint4*)(abits + ((size_t)(n * H + iy) * Wd + ix) * WW);
#pragma unroll
                for (int g4 = 0; g4 < WG; g4++) {
                    uint4 a = __ldg(ap + g4);
                    uint4 wv = sw[(tap * WG + g4) * 32 + lane];
                    s += __popc(a.x ^ wv.x);
                    s += __popc(a.y ^ wv.y);
                    s += __popc(a.z ^ wv.z);
                    s += __popc(a.w ^ wv.w);
                }
            }
        }
        return valid * WW * 32 - 2 * s;
    };

    int p0 = (blockIdx.x * 8 + warp) * PPW;
    for (int pp = 0; pp < PPW; pp++) {
        int p = p0 + pp;
        if (p >= npix) break;   // warp-uniform
        int xo = p % Wo;
        int t = p / Wo;
        int yo = t % Ho;
        int n = t / Ho;

        int m;
        if (POOL) {
            m = 0;  // relu(max) == max(relu, 0), accumulator is integer
            m = max(m, dot(n, 2 * yo + 0, 2 * xo + 0));
            m = max(m, dot(n, 2 * yo + 0, 2 * xo + 1));
            m = max(m, dot(n, 2 * yo + 1, 2 * xo + 0));
            m = max(m, dot(n, 2 * yo + 1, 2 * xo + 1));
        } else {
            m = max(dot(n, yo, xo), 0);
        }
        float val = fmaf((float)m, sc, bi);
        if (FINAL) {
            ofloat[(size_t)p * COUT + c] = val;
        } else {
            unsigned mask = __ballot_sync(0xffffffffu, val > 0.0f);
            if (lane == 0) obits[p * (COUT >> 5) + g] = mask;
        }
    }
}

// ---------------------------------------------------------------------------
// Dense (512->10) + softmax, one warp per output pixel.
// ---------------------------------------------------------------------------
__global__ void dense_softmax_kernel(const float* __restrict__ h, const float* __restrict__ dw,
                                     const float* __restrict__ db, float* __restrict__ out) {
    int warp = (blockIdx.x * blockDim.x + threadIdx.x) >> 5;
    int lane = threadIdx.x & 31;
    if (warp >= NB * 4 * 4) return;
    float acc[10];
#pragma unroll
    for (int j = 0; j < 10; j++) acc[j] = 0.0f;
    const float* hp = h + (size_t)warp * 512;
#pragma unroll
    for (int k = 0; k < 16; k++) {
        int cc = k * 32 + lane;
        float hv = hp[cc];
        const float* wp = dw + cc * 10;
#pragma unroll
        for (int j = 0; j < 10; j++) acc[j] = fmaf(hv, __ldg(wp + j), acc[j]);
    }
#pragma unroll
    for (int s = 16; s > 0; s >>= 1) {
#pragma unroll
        for (int j = 0; j < 10; j++) acc[j] += __shfl_xor_sync(0xffffffffu, acc[j], s);
    }
    if (lane == 0) {
        float l[10], m = -1e30f;
#pragma unroll
        for (int j = 0; j < 10; j++) { l[j] = acc[j] + db[j]; m = fmaxf(m, l[j]); }
        float sum = 0.0f;
#pragma unroll
        for (int j = 0; j < 10; j++) { l[j] = expf(l[j] - m); sum += l[j]; }
        float inv = 1.0f / sum;
#pragma unroll
        for (int j = 0; j < 10; j++) out[warp * 10 + j] = l[j] * inv;
    }
}

// ---------------------------------------------------------------------------
// Launch. Input order: 0:x 1:w1 2:b1 3:w2 4:w3 5:w4 6:w5 7:w6
//  8..19: bn{1..6}_scale/bias interleaved, 20:dense_w 21:dense_b
// ---------------------------------------------------------------------------
extern "C" void kernel_launch(void* const* d_in, const int* in_sizes, int n_in,
                              void* d_out, int out_size) {
    const float* x   = (const float*)d_in[0];
    const float* w1  = (const float*)d_in[1];
    const float* b1  = (const float*)d_in[2];
    const float* w2  = (const float*)d_in[3];
    const float* w3  = (const float*)d_in[4];
    const float* w4  = (const float*)d_in[5];
    const float* w5  = (const float*)d_in[6];
    const float* w6  = (const float*)d_in[7];
    const float* bn1s = (const float*)d_in[8];
    const float* bn1b = (const float*)d_in[9];
    const float* bn2s = (const float*)d_in[10];
    const float* bn2b = (const float*)d_in[11];
    const float* bn3s = (const float*)d_in[12];
    const float* bn3b = (const float*)d_in[13];
    const float* bn4s = (const float*)d_in[14];
    const float* bn4b = (const float*)d_in[15];
    const float* bn5s = (const float*)d_in[16];
    const float* bn5b = (const float*)d_in[17];
    const float* bn6s = (const float*)d_in[18];
    const float* bn6b = (const float*)d_in[19];
    const float* dw   = (const float*)d_in[20];
    const float* db   = (const float*)d_in[21];
    float* out = (float*)d_out;

    uint32_t *bits1, *bits2, *bits3, *bits4, *bits5;
    uint32_t *wb2, *wb3, *wb4, *wb5, *wb6;
    float* h6;
    cudaGetSymbolAddress((void**)&bits1, g_bits1);
    cudaGetSymbolAddress((void**)&bits2, g_bits2);
    cudaGetSymbolAddress((void**)&bits3, g_bits3);
    cudaGetSymbolAddress((void**)&bits4, g_bits4);
    cudaGetSymbolAddress((void**)&bits5, g_bits5);
    cudaGetSymbolAddress((void**)&wb2, g_wb2);
    cudaGetSymbolAddress((void**)&wb3, g_wb3);
    cudaGetSymbolAddress((void**)&wb4, g_wb4);
    cudaGetSymbolAddress((void**)&wb5, g_wb5);
    cudaGetSymbolAddress((void**)&wb6, g_wb6);
    cudaGetSymbolAddress((void**)&h6, g_h6);

    // 0: fused weight packing (all 5 layers in one launch)
    const int npack = 9 * 4 * 128 + 9 * 4 * 256 + 9 * 8 * 256 + 9 * 8 * 512 + 9 * 16 * 512;
    pack_all_kernel<<<(npack + 255) / 256, 256>>>(w2, w3, w4, w5, w6,
                                                  wb2, wb3, wb4, wb5, wb6);

    // 1: conv1 + relu + bn1 + binarize
    conv1_kernel<<<NB * 32 * 32, 128>>>(x, w1, b1, bn1s, bn1b, bits1);

    // 2: bconv2 (128->128) + pool + bn2
    bconv_kernel<4, true, false><<<dim3(NB * 16 * 16 / 32, 4), 256>>>(
        bits1, wb2, bn2s, bn2b, bits2, nullptr, NB, 32, 32, 128);
    // 3: bconv3 (128->256) + bn3
    bconv_kernel<4, false, false><<<dim3(NB * 16 * 16 / 32, 8), 256>>>(
        bits2, wb3, bn3s, bn3b, bits3, nullptr, NB, 16, 16, 256);
    // 4: bconv4 (256->256) + pool + bn4
    bconv_kernel<8, true, false><<<dim3(NB * 8 * 8 / 32, 8), 256>>>(
        bits3, wb4, bn4s, bn4b, bits4, nullptr, NB, 16, 16, 256);
    // 5: bconv5 (256->512) + bn5   (profiled slot under -s 5 -c 1)
    bconv_kernel<8, false, false><<<dim3(NB * 8 * 8 / 32, 16), 256>>>(
        bits4, wb5, bn5s, bn5b, bits5, nullptr, NB, 8, 8, 512);
    // 6: bconv6 (512->512) + pool + bn6 -> float
    bconv_kernel<16, true, true><<<dim3(NB * 4 * 4 / 32, 16), 256>>>(
        bits5, wb6, bn6s, bn6b, nullptr, h6, NB, 8, 8, 512);

    // 7: dense + softmax
    dense_softmax_kernel<<<NB * 4 * 4 * 32 / 256, 256>>>(h6, dw, db, out);
}

// round 3
// speedup vs baseline: 1.1628x; 1.0049x over previous
#include <cuda_runtime.h>
#include <cuda_bf16.h>
#include <cstdint>
#include <math.h>

// ---------------------------------------------------------------------------
// Binarized CNN (XNOR-net) forward pass. Bit-packed XNOR-popcount convs.
//   dot = valid_taps*Cin - 2 * sum_taps popc(abits ^ wbits)
// R3: compile-time shapes (templates), weights held in REGISTERS for
//     WW<=8 layers (no SMEM/LDS at all), warp-per-output-row mapping
//     (no per-pixel div/mod), uniform branches.
// ---------------------------------------------------------------------------

#define NB 128

// Scratch (device globals; no allocation allowed)
__device__ uint32_t g_bits1[NB * 32 * 32 * 4];
__device__ uint32_t g_bits2[NB * 16 * 16 * 4];
__device__ uint32_t g_bits3[NB * 16 * 16 * 8];
__device__ uint32_t g_bits4[NB * 8 * 8 * 8];
__device__ uint32_t g_bits5[NB * 8 * 8 * 16];
__device__ float    g_h6[NB * 4 * 4 * 512];
__device__ uint32_t g_wb2[9 * 4 * 128];
__device__ uint32_t g_wb3[9 * 4 * 256];
__device__ uint32_t g_wb4[9 * 8 * 256];
__device__ uint32_t g_wb5[9 * 8 * 512];
__device__ uint32_t g_wb6[9 * 16 * 512];

// ---------------------------------------------------------------------------
// Fused weight-sign packing for all 5 binary layers.
// Layout per layer: [tap(9)][cin_word][cout], bit j = cin%32.
// ---------------------------------------------------------------------------
__device__ __forceinline__ void pack_one(const float* __restrict__ w,
                                         uint32_t* __restrict__ wb,
                                         int idx, int CIN, int COUT) {
    int cout = idx % COUT;
    int tw = idx / COUT;            // tap*cw + wword
    int cw = CIN >> 5;
    int wword = tw % cw;
    int tap = tw / cw;
    uint32_t m = 0;
#pragma unroll 8
    for (int j = 0; j < 32; j++) {
        float f = w[(tap * CIN + wword * 32 + j) * COUT + cout];
        m |= (f > 0.0f ? 1u : 0u) << j;
    }
    wb[idx] = m;
}

__global__ void pack_all_kernel(const float* __restrict__ w2, const float* __restrict__ w3,
                                const float* __restrict__ w4, const float* __restrict__ w5,
                                const float* __restrict__ w6,
                                uint32_t* __restrict__ wb2, uint32_t* __restrict__ wb3,
                                uint32_t* __restrict__ wb4, uint32_t* __restrict__ wb5,
                                uint32_t* __restrict__ wb6) {
    int idx = blockIdx.x * blockDim.x + threadIdx.x;
    const int n2 = 9 * 4 * 128, n3 = 9 * 4 * 256, n4 = 9 * 8 * 256,
              n5 = 9 * 8 * 512, n6 = 9 * 16 * 512;
    if (idx < n2) { pack_one(w2, wb2, idx, 128, 128); return; }
    idx -= n2;
    if (idx < n3) { pack_one(w3, wb3, idx, 128, 256); return; }
    idx -= n3;
    if (idx < n4) { pack_one(w4, wb4, idx, 256, 256); return; }
    idx -= n4;
    if (idx < n5) { pack_one(w5, wb5, idx, 256, 512); return; }
    idx -= n5;
    if (idx < n6) { pack_one(w6, wb6, idx, 512, 512); return; }
}

// ---------------------------------------------------------------------------
// conv1: float 3x3 SAME conv (3->128) + bias + relu + bn + binarize + pack
// ---------------------------------------------------------------------------
__global__ void conv1_kernel(const float* __restrict__ x, const float* __restrict__ w1,
                             const float* __restrict__ b1, const float* __restrict__ s1,
                             const float* __restrict__ bb1, uint32_t* __restrict__ obits) {
    int p = blockIdx.x;                  // 0 .. 128*32*32-1
    int co = threadIdx.x;                // 0..127
    int xx = p & 31;
    int y = (p >> 5) & 31;
    int n = p >> 10;
    float acc = 0.0f;
#pragma unroll
    for (int ky = 0; ky < 3; ky++) {
        int iy = y + ky - 1;
        if ((unsigned)iy >= 32u) continue;
#pragma unroll
        for (int kx = 0; kx < 3; kx++) {
            int ix = xx + kx - 1;
            if ((unsigned)ix >= 32u) continue;
            const float* xp = x + ((n * 32 + iy) * 32 + ix) * 3;
            const float* wp = w1 + ((ky * 3 + kx) * 3) * 128 + co;
            acc = fmaf(xp[0], wp[0], acc);
            acc = fmaf(xp[1], wp[128], acc);
            acc = fmaf(xp[2], wp[256], acc);
        }
    }
    float v = fmaxf(acc + b1[co], 0.0f);
    v = fmaf(v, s1[co], bb1[co]);
    unsigned mask = __ballot_sync(0xffffffffu, v > 0.0f);
    if ((co & 31) == 0) obits[p * 4 + (co >> 5)] = mask;
}

// ---------------------------------------------------------------------------
// Generic binary conv layer, compile-time shapes.
//   warp -> one output row (row = n*Ho + yo), lane -> cout = g*32 + lane.
//   WW<=8: 9*WW weight words live in REGISTERS (loaded coalesced from gmem).
//   WW==16: weights staged in SMEM, LDS.128 per tap (reg budget).
//   Activations: broadcast LDG.128 (all lanes same address).
// Grid: x = N*Ho/8, y = COUT/32.
// ---------------------------------------------------------------------------
template <int H, int W, int WW, int COUT, bool POOL, bool FINAL>
__global__ void __launch_bounds__(256) bconv_kernel(
    const uint32_t* __restrict__ abits, const uint32_t* __restrict__ wbits,
    const float* __restrict__ scale, const float* __restrict__ bias,
    uint32_t* __restrict__ obits, float* __restrict__ ofloat) {
    constexpr int Ho = POOL ? H / 2 : H;
    constexpr int Wo = POOL ? W / 2 : W;
    constexpr int WG = WW / 4;
    constexpr bool REGW = (WW <= 8);

    const int lane = threadIdx.x & 31;
    const int warp = threadIdx.x >> 5;
    const int row = blockIdx.x * 8 + warp;   // n*Ho + yo
    const int g = blockIdx.y;
    const int n = row / Ho;                  // Ho is power of two -> shift
    const int yo = row - n * Ho;
    const int c = g * 32 + lane;

    // Weights
    uint32_t wreg[REGW ? 9 * WW : 1];
    __shared__ uint4 sw[REGW ? 1 : 9 * WG * 32];
    if constexpr (REGW) {
#pragma unroll
        for (int t = 0; t < 9 * WW; t++) wreg[t] = __ldg(wbits + t * COUT + c);
    } else {
        uint32_t* sws = (uint32_t*)sw;
        for (int f = threadIdx.x; f < 9 * WW * 32; f += 256) {
            int j = f & 3;
            int ln = (f >> 2) & 31;
            int tg = f >> 7;               // tap*WG + g4
            int tap = tg / WG;
            int g4 = tg - tap * WG;
            sws[f] = wbits[(tap * WW + g4 * 4 + j) * COUT + g * 32 + ln];
        }
        __syncthreads();
    }

    const float sc = scale[c];
    const float bi = bias[c];
    const uint32_t* abase = abits + (size_t)n * H * W * WW;

    auto dotf = [&](int y, int x) -> int {
        int s = 0, valid = 0;
#pragma unroll
        for (int ky = 0; ky < 3; ky++) {
            int iy = y + ky - 1;
            if ((unsigned)iy >= (unsigned)H) continue;
#pragma unroll
            for (int kx = 0; kx < 3; kx++) {
                int ix = x + kx - 1;
                if ((unsigned)ix >= (unsigned)W) continue;
                valid++;
                const uint4* ap = (const uint4*)(abase + ((size_t)iy * W + ix) * WW);
#pragma unroll
                for (int g4 = 0; g4 < WG; g4++) {
                    uint4 a = __ldg(ap + g4);
                    if constexpr (REGW) {
                        int t = (ky * 3 + kx) * WW + g4 * 4;
                        s += __popc(a.x ^ wreg[t]) + __popc(a.y ^ wreg[t + 1]) +
                             __popc(a.z ^ wreg[t + 2]) + __popc(a.w ^ wreg[t + 3]);
                    } else {
                        uint4 wv = sw[((ky * 3 + kx) * WG + g4) * 32 + lane];
                        s += __popc(a.x ^ wv.x) + __popc(a.y ^ wv.y) +
                             __popc(a.z ^ wv.z) + __popc(a.w ^ wv.w);
                    }
                }
            }
        }
        return valid * WW * 32 - 2 * s;
    };

#pragma unroll 1
    for (int xo = 0; xo < Wo; xo++) {
        int m;
        if constexpr (POOL) {
            m = 0;  // relu(max) == max(relu, 0); accumulator is integer
            m = max(m, dotf(2 * yo + 0, 2 * xo + 0));
            m = max(m, dotf(2 * yo + 0, 2 * xo + 1));
            m = max(m, dotf(2 * yo + 1, 2 * xo + 0));
            m = max(m, dotf(2 * yo + 1, 2 * xo + 1));
        } else {
            m = max(dotf(yo, xo), 0);
        }
        float val = fmaf((float)m, sc, bi);
        if constexpr (FINAL) {
            ofloat[((size_t)row * Wo + xo) * COUT + c] = val;
        } else {
            unsigned mask = __ballot_sync(0xffffffffu, val > 0.0f);
            if (lane == 0) obits[((size_t)row * Wo + xo) * (COUT / 32) + g] = mask;
        }
    }
}

// ---------------------------------------------------------------------------
// Dense (512->10) + softmax, one warp per output pixel.
// ---------------------------------------------------------------------------
__global__ void dense_softmax_kernel(const float* __restrict__ h, const float* __restrict__ dw,
                                     const float* __restrict__ db, float* __restrict__ out) {
    int warp = (blockIdx.x * blockDim.x + threadIdx.x) >> 5;
    int lane = threadIdx.x & 31;
    if (warp >= NB * 4 * 4) return;
    float acc[10];
#pragma unroll
    for (int j = 0; j < 10; j++) acc[j] = 0.0f;
    const float* hp = h + (size_t)warp * 512;
#pragma unroll
    for (int k = 0; k < 16; k++) {
        int cc = k * 32 + lane;
        float hv = hp[cc];
        const float* wp = dw + cc * 10;
#pragma unroll
        for (int j = 0; j < 10; j++) acc[j] = fmaf(hv, __ldg(wp + j), acc[j]);
    }
#pragma unroll
    for (int s = 16; s > 0; s >>= 1) {
#pragma unroll
        for (int j = 0; j < 10; j++) acc[j] += __shfl_xor_sync(0xffffffffu, acc[j], s);
    }
    if (lane == 0) {
        float l[10], m = -1e30f;
#pragma unroll
        for (int j = 0; j < 10; j++) { l[j] = acc[j] + db[j]; m = fmaxf(m, l[j]); }
        float sum = 0.0f;
#pragma unroll
        for (int j = 0; j < 10; j++) { l[j] = expf(l[j] - m); sum += l[j]; }
        float inv = 1.0f / sum;
#pragma unroll
        for (int j = 0; j < 10; j++) out[warp * 10 + j] = l[j] * inv;
    }
}

// ---------------------------------------------------------------------------
// Launch. Input order: 0:x 1:w1 2:b1 3:w2 4:w3 5:w4 6:w5 7:w6
//  8..19: bn{1..6}_scale/bias interleaved, 20:dense_w 21:dense_b
// ---------------------------------------------------------------------------
extern "C" void kernel_launch(void* const* d_in, const int* in_sizes, int n_in,
                              void* d_out, int out_size) {
    const float* x   = (const float*)d_in[0];
    const float* w1  = (const float*)d_in[1];
    const float* b1  = (const float*)d_in[2];
    const float* w2  = (const float*)d_in[3];
    const float* w3  = (const float*)d_in[4];
    const float* w4  = (const float*)d_in[5];
    const float* w5  = (const float*)d_in[6];
    const float* w6  = (const float*)d_in[7];
    const float* bn1s = (const float*)d_in[8];
    const float* bn1b = (const float*)d_in[9];
    const float* bn2s = (const float*)d_in[10];
    const float* bn2b = (const float*)d_in[11];
    const float* bn3s = (const float*)d_in[12];
    const float* bn3b = (const float*)d_in[13];
    const float* bn4s = (const float*)d_in[14];
    const float* bn4b = (const float*)d_in[15];
    const float* bn5s = (const float*)d_in[16];
    const float* bn5b = (const float*)d_in[17];
    const float* bn6s = (const float*)d_in[18];
    const float* bn6b = (const float*)d_in[19];
    const float* dw   = (const float*)d_in[20];
    const float* db   = (const float*)d_in[21];
    float* out = (float*)d_out;

    uint32_t *bits1, *bits2, *bits3, *bits4, *bits5;
    uint32_t *wb2, *wb3, *wb4, *wb5, *wb6;
    float* h6;
    cudaGetSymbolAddress((void**)&bits1, g_bits1);
    cudaGetSymbolAddress((void**)&bits2, g_bits2);
    cudaGetSymbolAddress((void**)&bits3, g_bits3);
    cudaGetSymbolAddress((void**)&bits4, g_bits4);
    cudaGetSymbolAddress((void**)&bits5, g_bits5);
    cudaGetSymbolAddress((void**)&wb2, g_wb2);
    cudaGetSymbolAddress((void**)&wb3, g_wb3);
    cudaGetSymbolAddress((void**)&wb4, g_wb4);
    cudaGetSymbolAddress((void**)&wb5, g_wb5);
    cudaGetSymbolAddress((void**)&wb6, g_wb6);
    cudaGetSymbolAddress((void**)&h6, g_h6);

    // 0: fused weight packing (all 5 layers in one launch)
    const int npack = 9 * 4 * 128 + 9 * 4 * 256 + 9 * 8 * 256 + 9 * 8 * 512 + 9 * 16 * 512;
    pack_all_kernel<<<(npack + 255) / 256, 256>>>(w2, w3, w4, w5, w6,
                                                  wb2, wb3, wb4, wb5, wb6);

    // 1: conv1 + relu + bn1 + binarize
    conv1_kernel<<<NB * 32 * 32, 128>>>(x, w1, b1, bn1s, bn1b, bits1);

    // 2: bconv2 (128->128) + pool + bn2      H=32 W=32 WW=4 COUT=128
    bconv_kernel<32, 32, 4, 128, true, false><<<dim3(NB * 16 / 8, 4), 256>>>(
        bits1, wb2, bn2s, bn2b, bits2, nullptr);
    // 3: bconv3 (128->256) + bn3             H=16 W=16 WW=4 COUT=256
    bconv_kernel<16, 16, 4, 256, false, false><<<dim3(NB * 16 / 8, 8), 256>>>(
        bits2, wb3, bn3s, bn3b, bits3, nullptr);
    // 4: bconv4 (256->256) + pool + bn4      H=16 W=16 WW=8 COUT=256
    bconv_kernel<16, 16, 8, 256, true, false><<<dim3(NB * 8 / 8, 8), 256>>>(
        bits3, wb4, bn4s, bn4b, bits4, nullptr);
    // 5: bconv5 (256->512) + bn5             H=8 W=8 WW=8 COUT=512  (profiled)
    bconv_kernel<8, 8, 8, 512, false, false><<<dim3(NB * 8 / 8, 16), 256>>>(
        bits4, wb5, bn5s, bn5b, bits5, nullptr);
    // 6: bconv6 (512->512) + pool + bn6 -> float   H=8 W=8 WW=16 COUT=512
    bconv_kernel<8, 8, 16, 512, true, true><<<dim3(NB * 4 / 8, 16), 256>>>(
        bits5, wb6, bn6s, bn6b, nullptr, h6);

    // 7: dense + softmax
    dense_softmax_kernel<<<NB * 4 * 4 * 32 / 256, 256>>>(h6, dw, db, out);
}